// round 1
// baseline (speedup 1.0000x reference)
#include <cuda_runtime.h>
#include <cstdint>

#define NN_MAX 100000
#define NE_MAX 1600000
#define D 128          // features
#define DV 32          // D/4 float4s per row
#define N_ITER 40

// ---------------- static device scratch (no allocations allowed) ----------------
__device__ int   g_idx64;          // 1 if edge_index is int64, 0 if int32
__device__ int   g_mask_i32;       // 1 if mask is int32, 0 if uint8/bool
__device__ int   g_deg[NN_MAX];
__device__ int   g_rowptr[NN_MAX + 1];
__device__ int   g_cursor[NN_MAX];
__device__ float g_dinv[NN_MAX];
__device__ int   g_col[NE_MAX];
__device__ float g_w[NE_MAX];
__device__ float g_buf[(size_t)NN_MAX * D];   // ping-pong partner of d_out (51.2 MB)

// ---------------- helpers ----------------
__device__ __forceinline__ long long load_idx(const void* p, long long e) {
    if (g_idx64) return ((const long long*)p)[e];
    return (long long)((const int*)p)[e];
}
__device__ __forceinline__ bool load_mask(const void* m, int i) {
    if (g_mask_i32) return ((const int*)m)[i] != 0;
    return ((const unsigned char*)m)[i] != 0;
}

// ---------------- kernels ----------------

// Detect dtypes of edge_index and mask from bit patterns.
// int64 indices < 100000 => every high 32-bit word is 0. For int32 data the odd
// words are random node ids (P(zero)=1e-5 each) -> P(all 64 zero) ~ 0.
// int32 mask of {0,1} => bytes at (i%4)!=0 are all 0. For uint8 mask those bytes
// are random {0,1} -> P(192 zeros) ~ 2^-192.
__global__ void detect_kernel(const void* eidx, const void* mask) {
    if (blockIdx.x != 0 || threadIdx.x != 0) return;
    const int* w = (const int*)eidx;
    int is64 = 1;
    for (int i = 0; i < 64; i++) {
        if (w[2 * i + 1] != 0) { is64 = 0; break; }
    }
    g_idx64 = is64;
    const unsigned char* b = (const unsigned char*)mask;
    int mi32 = 1;
    for (int i = 0; i < 256; i++) {
        if ((i & 3) != 0 && b[i] != 0) { mi32 = 0; break; }
    }
    g_mask_i32 = mi32;
}

__global__ void zero_kernel(int n) {
    int i = blockIdx.x * blockDim.x + threadIdx.x;
    if (i < n) { g_deg[i] = 0; g_cursor[i] = 0; }
}

__global__ void count_kernel(const void* eidx, long long ne) {
    long long e = (long long)blockIdx.x * blockDim.x + threadIdx.x;
    if (e >= ne) return;
    int r = (int)load_idx(eidx, e);
    atomicAdd(&g_deg[r], 1);
}

// Single-block exclusive scan of g_deg -> g_rowptr, plus dinv = rsqrt(deg).
__global__ void scan_kernel(int n) {
    __shared__ int sh[1024];
    __shared__ int carry_sh;
    int tid = threadIdx.x;
    if (tid == 0) carry_sh = 0;
    __syncthreads();
    int ntiles = (n + 1023) / 1024;
    for (int t = 0; t < ntiles; t++) {
        int i = t * 1024 + tid;
        int v = (i < n) ? g_deg[i] : 0;
        sh[tid] = v;
        __syncthreads();
        #pragma unroll
        for (int off = 1; off < 1024; off <<= 1) {
            int add = (tid >= off) ? sh[tid - off] : 0;
            __syncthreads();
            sh[tid] += add;
            __syncthreads();
        }
        if (i < n) {
            g_rowptr[i] = carry_sh + sh[tid] - v;
            g_dinv[i]   = (v > 0) ? rsqrtf((float)v) : 0.0f;
        }
        __syncthreads();
        if (tid == 0) carry_sh += sh[1023];
        __syncthreads();
    }
    if (tid == 0) g_rowptr[n] = carry_sh;
}

__global__ void scatter_kernel(const void* eidx, long long ne) {
    long long e = (long long)blockIdx.x * blockDim.x + threadIdx.x;
    if (e >= ne) return;
    int r = (int)load_idx(eidx, e);
    int c = (int)load_idx(eidx, e + ne);
    int pos = g_rowptr[r] + atomicAdd(&g_cursor[r], 1);
    g_col[pos] = c;
    g_w[pos]   = g_dinv[r] * g_dinv[c];
}

// out0 = mask ? x : 0 in BOTH buffers (masked rows are never rewritten after this).
__global__ void init_kernel(const float4* __restrict__ x, float4* __restrict__ out,
                            const void* mask, int n) {
    long long i = (long long)blockIdx.x * blockDim.x + threadIdx.x;
    long long total = (long long)n * DV;
    if (i >= total) return;
    int node = (int)(i >> 5);   // i / DV
    float4 v = make_float4(0.f, 0.f, 0.f, 0.f);
    if (load_mask(mask, node)) v = x[i];
    out[i] = v;
    ((float4*)g_buf)[i] = v;
}

// One warp per row; lane owns 4 features (float4). Masked rows skipped entirely.
__global__ void __launch_bounds__(256) spmm_kernel(const float4* __restrict__ prev,
                                                   float4* __restrict__ next,
                                                   const void* mask, int n) {
    int warp = (blockIdx.x * blockDim.x + threadIdx.x) >> 5;
    int lane = threadIdx.x & 31;
    if (warp >= n) return;
    if (load_mask(mask, warp)) return;

    int s = g_rowptr[warp];
    int e = g_rowptr[warp + 1];

    float4 acc0 = make_float4(0.f, 0.f, 0.f, 0.f);
    float4 acc1 = make_float4(0.f, 0.f, 0.f, 0.f);
    int j = s;
    for (; j + 1 < e; j += 2) {
        int   c0 = __ldg(&g_col[j]);
        float w0 = __ldg(&g_w[j]);
        int   c1 = __ldg(&g_col[j + 1]);
        float w1 = __ldg(&g_w[j + 1]);
        float4 v0 = __ldg(&prev[(long long)c0 * DV + lane]);
        float4 v1 = __ldg(&prev[(long long)c1 * DV + lane]);
        acc0.x = fmaf(w0, v0.x, acc0.x); acc0.y = fmaf(w0, v0.y, acc0.y);
        acc0.z = fmaf(w0, v0.z, acc0.z); acc0.w = fmaf(w0, v0.w, acc0.w);
        acc1.x = fmaf(w1, v1.x, acc1.x); acc1.y = fmaf(w1, v1.y, acc1.y);
        acc1.z = fmaf(w1, v1.z, acc1.z); acc1.w = fmaf(w1, v1.w, acc1.w);
    }
    if (j < e) {
        int   c0 = __ldg(&g_col[j]);
        float w0 = __ldg(&g_w[j]);
        float4 v0 = __ldg(&prev[(long long)c0 * DV + lane]);
        acc0.x = fmaf(w0, v0.x, acc0.x); acc0.y = fmaf(w0, v0.y, acc0.y);
        acc0.z = fmaf(w0, v0.z, acc0.z); acc0.w = fmaf(w0, v0.w, acc0.w);
    }
    acc0.x += acc1.x; acc0.y += acc1.y; acc0.z += acc1.z; acc0.w += acc1.w;
    next[(long long)warp * DV + lane] = acc0;
}

// ---------------- launch ----------------
extern "C" void kernel_launch(void* const* d_in, const int* in_sizes, int n_in,
                              void* d_out, int out_size) {
    const float* x    = (const float*)d_in[0];
    const void*  eidx = d_in[1];
    const void*  mask = d_in[2];
    float*       out  = (float*)d_out;

    int       n  = in_sizes[0] / D;       // 100000
    long long ne = in_sizes[1] / 2;       // 1600000

    float* buf = nullptr;
    cudaGetSymbolAddress((void**)&buf, g_buf);

    // preprocessing (once per launch, amortized over 40 iterations)
    detect_kernel<<<1, 32>>>(eidx, mask);
    zero_kernel<<<(n + 255) / 256, 256>>>(n);
    count_kernel<<<(int)((ne + 255) / 256), 256>>>(eidx, ne);
    scan_kernel<<<1, 1024>>>(n);
    scatter_kernel<<<(int)((ne + 255) / 256), 256>>>(eidx, ne);

    long long tot4 = (long long)n * DV;
    init_kernel<<<(int)((tot4 + 255) / 256), 256>>>((const float4*)x, (float4*)out, mask, n);

    // 40 iterations, ping-pong. Even count => final result lands in d_out.
    int grid = (n * 32 + 255) / 256;  // 8 warps (rows) per 256-thread CTA
    for (int it = 0; it < N_ITER; it++) {
        const float* prev = (it & 1) ? buf : out;
        float*       next = (it & 1) ? out : buf;
        spmm_kernel<<<grid, 256>>>((const float4*)prev, (float4*)next, mask, n);
    }
}

// round 2
// speedup vs baseline: 1.0003x; 1.0003x over previous
#include <cuda_runtime.h>
#include <cstdint>

#define NN_MAX 100000
#define NE_MAX 1600000
#define D 128          // features
#define DV 32          // D/4 float4s per row
#define N_ITER 40

// ---------------- static device scratch (no allocations allowed) ----------------
__device__ int   g_idx64;          // 1 if edge_index is int64, 0 if int32
__device__ int   g_mask_i32;       // 1 if mask is int32, 0 if uint8/bool
__device__ int   g_deg[NN_MAX];
__device__ int   g_rowptr[NN_MAX + 1];
__device__ int   g_cursor[NN_MAX];
__device__ float g_dinv[NN_MAX];
__device__ int   g_col[NE_MAX];
__device__ float g_w[NE_MAX];
__device__ float g_buf[(size_t)NN_MAX * D];   // ping-pong partner of d_out (51.2 MB)

// ---------------- helpers ----------------
__device__ __forceinline__ long long load_idx(const void* p, long long e) {
    if (g_idx64) return ((const long long*)p)[e];
    return (long long)((const int*)p)[e];
}
__device__ __forceinline__ bool load_mask(const void* m, int i) {
    if (g_mask_i32) return ((const int*)m)[i] != 0;
    return ((const unsigned char*)m)[i] != 0;
}

// ---------------- kernels ----------------

// Detect dtypes of edge_index and mask from bit patterns.
// int64 indices < 100000 => every high 32-bit word is 0. For int32 data the odd
// words are random node ids (P(zero)=1e-5 each) -> P(all 64 zero) ~ 0.
// int32 mask of {0,1} => bytes at (i%4)!=0 are all 0. For uint8 mask those bytes
// are random {0,1} -> P(192 zeros) ~ 2^-192.
__global__ void detect_kernel(const void* eidx, const void* mask) {
    if (blockIdx.x != 0 || threadIdx.x != 0) return;
    const int* w = (const int*)eidx;
    int is64 = 1;
    for (int i = 0; i < 64; i++) {
        if (w[2 * i + 1] != 0) { is64 = 0; break; }
    }
    g_idx64 = is64;
    const unsigned char* b = (const unsigned char*)mask;
    int mi32 = 1;
    for (int i = 0; i < 256; i++) {
        if ((i & 3) != 0 && b[i] != 0) { mi32 = 0; break; }
    }
    g_mask_i32 = mi32;
}

__global__ void zero_kernel(int n) {
    int i = blockIdx.x * blockDim.x + threadIdx.x;
    if (i < n) { g_deg[i] = 0; g_cursor[i] = 0; }
}

__global__ void count_kernel(const void* eidx, long long ne) {
    long long e = (long long)blockIdx.x * blockDim.x + threadIdx.x;
    if (e >= ne) return;
    int r = (int)load_idx(eidx, e);
    atomicAdd(&g_deg[r], 1);
}

// Single-block exclusive scan of g_deg -> g_rowptr, plus dinv = rsqrt(deg).
__global__ void scan_kernel(int n) {
    __shared__ int sh[1024];
    __shared__ int carry_sh;
    int tid = threadIdx.x;
    if (tid == 0) carry_sh = 0;
    __syncthreads();
    int ntiles = (n + 1023) / 1024;
    for (int t = 0; t < ntiles; t++) {
        int i = t * 1024 + tid;
        int v = (i < n) ? g_deg[i] : 0;
        sh[tid] = v;
        __syncthreads();
        #pragma unroll
        for (int off = 1; off < 1024; off <<= 1) {
            int add = (tid >= off) ? sh[tid - off] : 0;
            __syncthreads();
            sh[tid] += add;
            __syncthreads();
        }
        if (i < n) {
            g_rowptr[i] = carry_sh + sh[tid] - v;
            g_dinv[i]   = (v > 0) ? rsqrtf((float)v) : 0.0f;
        }
        __syncthreads();
        if (tid == 0) carry_sh += sh[1023];
        __syncthreads();
    }
    if (tid == 0) g_rowptr[n] = carry_sh;
}

__global__ void scatter_kernel(const void* eidx, long long ne) {
    long long e = (long long)blockIdx.x * blockDim.x + threadIdx.x;
    if (e >= ne) return;
    int r = (int)load_idx(eidx, e);
    int c = (int)load_idx(eidx, e + ne);
    int pos = g_rowptr[r] + atomicAdd(&g_cursor[r], 1);
    g_col[pos] = c;
    g_w[pos]   = g_dinv[r] * g_dinv[c];
}

// out0 = mask ? x : 0 in BOTH buffers (masked rows are never rewritten after this).
__global__ void init_kernel(const float4* __restrict__ x, float4* __restrict__ out,
                            const void* mask, int n) {
    long long i = (long long)blockIdx.x * blockDim.x + threadIdx.x;
    long long total = (long long)n * DV;
    if (i >= total) return;
    int node = (int)(i >> 5);   // i / DV
    float4 v = make_float4(0.f, 0.f, 0.f, 0.f);
    if (load_mask(mask, node)) v = x[i];
    out[i] = v;
    ((float4*)g_buf)[i] = v;
}

// One warp per row; lane owns 4 features (float4). Masked rows skipped entirely.
__global__ void __launch_bounds__(256) spmm_kernel(const float4* __restrict__ prev,
                                                   float4* __restrict__ next,
                                                   const void* mask, int n) {
    int warp = (blockIdx.x * blockDim.x + threadIdx.x) >> 5;
    int lane = threadIdx.x & 31;
    if (warp >= n) return;
    if (load_mask(mask, warp)) return;

    int s = g_rowptr[warp];
    int e = g_rowptr[warp + 1];

    float4 acc0 = make_float4(0.f, 0.f, 0.f, 0.f);
    float4 acc1 = make_float4(0.f, 0.f, 0.f, 0.f);
    int j = s;
    for (; j + 1 < e; j += 2) {
        int   c0 = __ldg(&g_col[j]);
        float w0 = __ldg(&g_w[j]);
        int   c1 = __ldg(&g_col[j + 1]);
        float w1 = __ldg(&g_w[j + 1]);
        float4 v0 = __ldg(&prev[(long long)c0 * DV + lane]);
        float4 v1 = __ldg(&prev[(long long)c1 * DV + lane]);
        acc0.x = fmaf(w0, v0.x, acc0.x); acc0.y = fmaf(w0, v0.y, acc0.y);
        acc0.z = fmaf(w0, v0.z, acc0.z); acc0.w = fmaf(w0, v0.w, acc0.w);
        acc1.x = fmaf(w1, v1.x, acc1.x); acc1.y = fmaf(w1, v1.y, acc1.y);
        acc1.z = fmaf(w1, v1.z, acc1.z); acc1.w = fmaf(w1, v1.w, acc1.w);
    }
    if (j < e) {
        int   c0 = __ldg(&g_col[j]);
        float w0 = __ldg(&g_w[j]);
        float4 v0 = __ldg(&prev[(long long)c0 * DV + lane]);
        acc0.x = fmaf(w0, v0.x, acc0.x); acc0.y = fmaf(w0, v0.y, acc0.y);
        acc0.z = fmaf(w0, v0.z, acc0.z); acc0.w = fmaf(w0, v0.w, acc0.w);
    }
    acc0.x += acc1.x; acc0.y += acc1.y; acc0.z += acc1.z; acc0.w += acc1.w;
    next[(long long)warp * DV + lane] = acc0;
}

// ---------------- launch ----------------
extern "C" void kernel_launch(void* const* d_in, const int* in_sizes, int n_in,
                              void* d_out, int out_size) {
    const float* x    = (const float*)d_in[0];
    const void*  eidx = d_in[1];
    const void*  mask = d_in[2];
    float*       out  = (float*)d_out;

    int       n  = in_sizes[0] / D;       // 100000
    long long ne = in_sizes[1] / 2;       // 1600000

    float* buf = nullptr;
    cudaGetSymbolAddress((void**)&buf, g_buf);

    // preprocessing (once per launch, amortized over 40 iterations)
    detect_kernel<<<1, 32>>>(eidx, mask);
    zero_kernel<<<(n + 255) / 256, 256>>>(n);
    count_kernel<<<(int)((ne + 255) / 256), 256>>>(eidx, ne);
    scan_kernel<<<1, 1024>>>(n);
    scatter_kernel<<<(int)((ne + 255) / 256), 256>>>(eidx, ne);

    long long tot4 = (long long)n * DV;
    init_kernel<<<(int)((tot4 + 255) / 256), 256>>>((const float4*)x, (float4*)out, mask, n);

    // 40 iterations, ping-pong. Even count => final result lands in d_out.
    int grid = (n * 32 + 255) / 256;  // 8 warps (rows) per 256-thread CTA
    for (int it = 0; it < N_ITER; it++) {
        const float* prev = (it & 1) ? buf : out;
        float*       next = (it & 1) ? out : buf;
        spmm_kernel<<<grid, 256>>>((const float4*)prev, (float4*)next, mask, n);
    }
}